// round 7
// baseline (speedup 1.0000x reference)
#include <cuda_runtime.h>
#include <cuda_bf16.h>

// DenseIouPred: 72x72 IoU map around ind[0], window radius r.
// Scatter inverts to per-pixel gather (valid offsets <-> in-range pixels 1:1,
// gather index == own flat index).
// R7: body unchanged (branchless, hoisted loads). Block-size series shows the
// only live lever: kernel 4.90(256t) -> 4.51(128t) -> 4.22(64t). Terminal
// step: 32 threads/CTA (one warp, zero intra-CTA arbitration), 162 CTAs all
// co-resident.

#define W 72
#define H 72
#define NPIX (W * H)   // 5184

__device__ int g_default_radius = 10;

__global__ void dense_iou_kernel(const float* __restrict__ out0,   // (4, W, H)
                                 const int*   __restrict__ ind,
                                 const float* __restrict__ tgt,    // 4 floats
                                 const int*   __restrict__ radius_p,
                                 float*       __restrict__ dst)    // (W, H)
{
    const int i = blockIdx.x * blockDim.x + threadIdx.x;
    if (i >= NPIX) return;

    // All loads issued unconditionally, mutually independent (MLP ~ 7).
    const int   ind0 = __ldg(ind);
    const int   r    = __ldg(radius_p);
    const float tl   = __ldg(tgt + 0);
    const float tr   = __ldg(tgt + 1);
    const float tt   = __ldg(tgt + 2);
    const float tb   = __ldg(tgt + 3);
    const float pl   = __ldg(out0 + 0 * NPIX + i);
    const float pr   = __ldg(out0 + 1 * NPIX + i);
    const float pt   = __ldg(out0 + 2 * NPIX + i);
    const float pb   = __ldg(out0 + 3 * NPIX + i);

    const int row = i / W;
    const int col = i - row * W;
    const int cw  = ind0 % W;
    const int ch  = ind0 / W;

    const int rw = col - cw;
    const int rh = row - ch;

    const float frw = (float)rw;
    const float frh = (float)rh;
    const float twl = tl + frw;
    const float twr = tr - frw;
    const float tht = tt + frh;
    const float thb = tb - frh;

    // Branchless validity
    const bool valid =
        (rw >= -r) & (rw <= r) & (rh >= -r) & (rh <= r) &
        (twl >= 0.0f) & (twr >= 0.0f) & (tht >= 0.0f) & (thb >= 0.0f);

    const float target_area = (twl + twr) * (tht + thb);
    const float pred_area   = (pl + pr) * (pt + pb);
    const float w_int = fminf(pl, twl) + fminf(pr, twr);
    const float h_int = fminf(pb, thb) + fminf(pt, tht);
    const float area_int   = w_int * h_int;
    const float area_union = target_area + pred_area - area_int;
    const float iou = __fdividef(area_int + 1.0f, area_union + 1.0f);

    dst[i] = valid ? iou : 0.0f;
}

extern "C" void kernel_launch(void* const* d_in, const int* in_sizes, int n_in,
                              void* d_out, int out_size)
{
    const float* output = (const float*)d_in[0];   // (128, 8, 4, 72, 72)
    const int*   ind    = (const int*)  d_in[1];   // (128, 8, 1)
    const float* target = (const float*)d_in[2];   // (128, 8, 4)
    float*       dst    = (float*)d_out;           // (72, 72)

    const int* radius = nullptr;
    if (n_in >= 4) {
        radius = (const int*)d_in[3];
    } else {
        void* p = nullptr;
        cudaGetSymbolAddress(&p, g_default_radius);  // capture-safe, no alloc
        radius = (const int*)p;
    }

    const int threads = 32;
    const int blocks  = (NPIX + threads - 1) / threads;  // 162 CTAs, one warp each
    dense_iou_kernel<<<blocks, threads>>>(output, ind, target, radius, dst);
}

// round 8
// speedup vs baseline: 1.0800x; 1.0800x over previous
#include <cuda_runtime.h>
#include <cuda_bf16.h>

// DenseIouPred: 72x72 IoU map around ind[0], window radius r.
// Scatter inverts to per-pixel gather (valid offsets <-> in-range pixels 1:1,
// gather index == own flat index).
// R8: block-size lever saturated at 64t (kernel 4.22us); harness-ncu gap
// correlates with grid size (41 CTAs gave best harness 5.12). Combine both:
// 41 CTAs x 64 threads, 2 pixels/thread via float2 (pairs never straddle a
// row since W=72 is even). Halves STG count vs scalar.

#define W 72
#define H 72
#define NPIX (W * H)     // 5184
#define NV2  (NPIX / 2)  // 2592 float2 groups

__device__ int g_default_radius = 10;

__global__ void dense_iou_kernel(const float2* __restrict__ out0,   // (4, W, H) as float2
                                 const int*    __restrict__ ind,
                                 const float*  __restrict__ tgt,    // 4 floats
                                 const int*    __restrict__ radius_p,
                                 float2*       __restrict__ dst)    // (W, H) as float2
{
    const int t = blockIdx.x * blockDim.x + threadIdx.x;
    if (t >= NV2) return;

    // All loads issued unconditionally, mutually independent (MLP ~ 7).
    const int    ind0 = __ldg(ind);
    const int    r    = __ldg(radius_p);
    const float  tl   = __ldg(tgt + 0);
    const float  tr   = __ldg(tgt + 1);
    const float  tt   = __ldg(tgt + 2);
    const float  tb   = __ldg(tgt + 3);
    const float2 pl2  = __ldg(out0 + 0 * NV2 + t);
    const float2 pr2  = __ldg(out0 + 1 * NV2 + t);
    const float2 pt2  = __ldg(out0 + 2 * NV2 + t);
    const float2 pb2  = __ldg(out0 + 3 * NV2 + t);

    const int cw = ind0 % W;
    const int ch = ind0 / W;

    // pixels 2t and 2t+1 share a row (W even)
    const int row  = t / (W / 2);             // t / 36
    const int col0 = (t - row * (W / 2)) * 2;

    const int   rh  = row - ch;
    const float frh = (float)rh;
    const float tht = tt + frh;
    const float thb = tb - frh;
    const bool  row_ok = (rh >= -r) & (rh <= r) & (tht >= 0.0f) & (thb >= 0.0f);

    float2 v;
    const float pls[2] = {pl2.x, pl2.y};
    const float prs[2] = {pr2.x, pr2.y};
    const float pts[2] = {pt2.x, pt2.y};
    const float pbs[2] = {pb2.x, pb2.y};
    float vs[2];
    #pragma unroll
    for (int j = 0; j < 2; j++) {
        const int   rw  = (col0 + j) - cw;
        const float frw = (float)rw;
        const float twl = tl + frw;
        const float twr = tr - frw;
        const bool valid = row_ok & (rw >= -r) & (rw <= r)
                         & (twl >= 0.0f) & (twr >= 0.0f);

        const float pl = pls[j], pr = prs[j], pt = pts[j], pb = pbs[j];
        const float target_area = (twl + twr) * (tht + thb);
        const float pred_area   = (pl + pr) * (pt + pb);
        const float w_int = fminf(pl, twl) + fminf(pr, twr);
        const float h_int = fminf(pb, thb) + fminf(pt, tht);
        const float area_int   = w_int * h_int;
        const float area_union = target_area + pred_area - area_int;
        const float iou = __fdividef(area_int + 1.0f, area_union + 1.0f);
        vs[j] = valid ? iou : 0.0f;
    }
    v.x = vs[0];
    v.y = vs[1];
    dst[t] = v;
}

extern "C" void kernel_launch(void* const* d_in, const int* in_sizes, int n_in,
                              void* d_out, int out_size)
{
    const float2* output = (const float2*)d_in[0];   // (128, 8, 4, 72, 72)
    const int*    ind    = (const int*)   d_in[1];   // (128, 8, 1)
    const float*  target = (const float*) d_in[2];   // (128, 8, 4)
    float2*       dst    = (float2*)d_out;           // (72, 72)

    const int* radius = nullptr;
    if (n_in >= 4) {
        radius = (const int*)d_in[3];
    } else {
        void* p = nullptr;
        cudaGetSymbolAddress(&p, g_default_radius);  // capture-safe, no alloc
        radius = (const int*)p;
    }

    const int threads = 64;
    const int blocks  = (NV2 + threads - 1) / threads;  // 41 CTAs
    dense_iou_kernel<<<blocks, threads>>>(output, ind, target, radius, dst);
}